// round 8
// baseline (speedup 1.0000x reference)
#include <cuda_runtime.h>
#include <math.h>

#define Hh 8
#define Dm 128
#define INSZ 512
#define OUTN 1024
#define HD 1024            // H*D rows
#define SLAB 16384         // D*D
#define SM_SZ 16777216     // H*D*D*D
#define OFF_S 512
#define OFF_SM 131584      // 512 + H*D*D
#define HEAD_BLKS 256

// scratch: k/q projections and per-row scalars
__device__ float g_k[HD], g_q[Dm];
__device__ float g_AL[HD], g_BA[HD], g_U[HD], g_CW[HD], g_CB[HD],
                 g_CV[HD], g_ALP[HD], g_CZ2[HD], g_y[HD];
__device__ int g_bar, g_done;   // software grid barrier (self-resetting)

// ---------------- kernel 1: fused head ----------------
// Phase A: k,q projections (warp-per-row GEMV). Grid barrier.
// Phase B: per-row w/z/b/v projections + scalars + S_new + y.
// 256 blocks x 256 threads, all resident (launch_bounds(256,2) -> >=296 slots).
__global__ void __launch_bounds__(256, 2) head_kernel(
    const float* __restrict__ x, const float* __restrict__ S,
    const float* __restrict__ Ww, const float* __restrict__ Wz,
    const float* __restrict__ Wb, const float* __restrict__ Wv,
    const float* __restrict__ Wk, const float* __restrict__ Wq,
    float* __restrict__ out) {
    int tid = threadIdx.x, bid = blockIdx.x;
    int lane = tid & 31;

    // ---- Phase A: k (1024 rows) + q (128 rows) ----
    int w = bid * 8 + (tid >> 5);         // global warp id, 0..2047
    if (w < HD + Dm) {
        const float4* wr = (w < HD) ? (const float4*)(Wk + (size_t)w * INSZ)
                                    : (const float4*)(Wq + (size_t)(w - HD) * INSZ);
        const float4* x4 = (const float4*)x;
        float s = 0.f;
        #pragma unroll
        for (int m = lane; m < INSZ / 4; m += 32) {
            float4 a = wr[m], b = x4[m];
            s += a.x * b.x + a.y * b.y + a.z * b.z + a.w * b.w;
        }
        #pragma unroll
        for (int o = 16; o; o >>= 1) s += __shfl_down_sync(0xffffffffu, s, o);
        if (lane == 0) {
            if (w < HD) g_k[w] = s;
            else        g_q[w - HD] = s;
        }
    }
    __threadfence();                      // publish this thread's stores
    __syncthreads();

    // ---- grid barrier ----
    if (tid == 0) {
        atomicAdd(&g_bar, 1);
        while (*(volatile int*)&g_bar < HEAD_BLKS) { }
        __threadfence();
    }
    __syncthreads();

    // ---- Phase B: 4 rows per block, two 128-thread groups x 2 rows ----
    int g  = tid >> 7;                    // group 0/1
    int j  = tid & 127;
    int wq = (tid >> 5) & 3;              // warp within group
    __shared__ float red[2][5][4];
    __shared__ float redy[2][4];
    __shared__ float sc[2][2];

    float4 xv = ((const float4*)x)[j];

    #pragma unroll
    for (int rr = 0; rr < 2; rr++) {
        int hi = bid * 4 + g * 2 + rr;    // 0..1023
        int h  = hi >> 7;
        size_t ro = (size_t)hi * (INSZ / 4);
        float4 aw = ((const float4*)Ww)[ro + j];
        float4 az = ((const float4*)Wz)[ro + j];
        float4 ab = ((const float4*)Wb)[ro + j];
        float4 av = ((const float4*)Wv)[ro + j];
        float pw = aw.x * xv.x + aw.y * xv.y + aw.z * xv.z + aw.w * xv.w;
        float pz = az.x * xv.x + az.y * xv.y + az.z * xv.z + az.w * xv.w;
        float pb = ab.x * xv.x + ab.y * xv.y + ab.z * xv.z + ab.w * xv.w;
        float pv = av.x * xv.x + av.y * xv.y + av.z * xv.z + av.w * xv.w;

        float kj = g_k[h * Dm + j];
        float Sj = S[(size_t)hi * Dm + j];
        float ps = Sj * kj;

        #pragma unroll
        for (int o = 16; o; o >>= 1) {
            pw += __shfl_down_sync(0xffffffffu, pw, o);
            pz += __shfl_down_sync(0xffffffffu, pz, o);
            pb += __shfl_down_sync(0xffffffffu, pb, o);
            pv += __shfl_down_sync(0xffffffffu, pv, o);
            ps += __shfl_down_sync(0xffffffffu, ps, o);
        }
        if (lane == 0) {
            red[g][0][wq] = pw; red[g][1][wq] = pz; red[g][2][wq] = pb;
            red[g][3][wq] = pv; red[g][4][wq] = ps;
        }
        __syncthreads();

        if (j == 0) {
            float ww = red[g][0][0] + red[g][0][1] + red[g][0][2] + red[g][0][3];
            float zz = red[g][1][0] + red[g][1][1] + red[g][1][2] + red[g][1][3];
            float bb = red[g][2][0] + red[g][2][1] + red[g][2][2] + red[g][2][3];
            float vv = red[g][3][0] + red[g][3][1] + red[g][3][2] + red[g][3][3];
            float sdot = red[g][4][0] + red[g][4][1] + red[g][4][2] + red[g][4][3];
            float gg = 1.f / (1.f + expf(-ww));
            float al = 1.f / (1.f + expf(-zz));
            float be = 1.f / (1.f + expf(-bb));
            float r_ = al * sdot;
            float u  = be * (gg * vv - r_);
            g_AL[hi] = al;
            g_BA[hi] = be * al;
            g_U[hi]  = u;
            g_CW[hi] = be * gg * (1.f - gg) * vv;
            g_CB[hi] = be * (1.f - be) * (gg * vv - r_);
            g_CV[hi] = be * gg;
            float alp = al * (1.f - al);
            g_ALP[hi] = alp;
            g_CZ2[hi] = alp * be * sdot;
            sc[g][0] = al; sc[g][1] = u;
        }
        __syncthreads();

        float al = sc[g][0], u = sc[g][1];
        float Snew = al * Sj + u * kj;
        out[OFF_S + (size_t)hi * Dm + j] = Snew;

        float yv = Snew * g_q[j];
        #pragma unroll
        for (int o = 16; o; o >>= 1) yv += __shfl_down_sync(0xffffffffu, yv, o);
        if (lane == 0) redy[g][wq] = yv;
        __syncthreads();
        if (j == 0) g_y[hi] = redy[g][0] + redy[g][1] + redy[g][2] + redy[g][3];
        __syncthreads();                  // red[] reuse next iteration
    }

    // ---- self-reset for next graph replay ----
    __threadfence();
    __syncthreads();
    if (tid == 0) {
        int d = atomicAdd(&g_done, 1);
        if (d == HEAD_BLKS - 1) { g_bar = 0; g_done = 0; }
    }
}

// ---------------- kernel 2: the 670MB sensitivity update ----------------
// Two blocks per (t,h,i) slab; each block handles 64 columns.
// 256 threads = (part 0..15, cq 0..15): thread owns 8 j-rows x 4 contiguous
// columns in registers as float4. 1 LDG.128 + 1 STG.128 per row.
// First 512 blocks also compute one row of y @ W_o^T + b_o.
__global__ void __launch_bounds__(256, 4) slab_kernel(
    const float* __restrict__ P0, const float* __restrict__ P1,
    const float* __restrict__ P2, const float* __restrict__ P3,
    const float* __restrict__ P4, const float* __restrict__ S,
    const float* __restrict__ Wo, const float* __restrict__ bo,
    float* __restrict__ out) {
    int bx  = blockIdx.x;         // 0..10239
    int tid = threadIdx.x;

    // folded output projection: out[row] = Wo[row,:] . y + bo[row]
    if (bx < INSZ && tid < 32) {
        const float4* wr = (const float4*)(Wo + (size_t)bx * OUTN);
        float s = 0.f;
        for (int m = tid; m < OUTN / 4; m += 32) {
            float4 a = wr[m];
            s += a.x * g_y[m * 4] + a.y * g_y[m * 4 + 1]
               + a.z * g_y[m * 4 + 2] + a.w * g_y[m * 4 + 3];
        }
        #pragma unroll
        for (int o = 16; o; o >>= 1) s += __shfl_down_sync(0xffffffffu, s, o);
        if (tid == 0) out[bx] = s + bo[bx];
    }

    int half = bx & 1;
    int sb   = bx >> 1;           // slab id 0..5119
    int t    = sb >> 10;
    int hi   = sb & 1023;
    int h    = hi >> 7;
    int i    = hi & 127;
    int cq   = tid & 15;
    int part = tid >> 4;          // 0..15, owns j in [part*8, part*8+8)
    int c0   = half * 64 + cq * 4;

    __shared__ float k_s[128], S_s[128];
    __shared__ float4 red4[16][16];
    if (tid < 128) {
        k_s[tid] = g_k[h * 128 + tid];
        S_s[tid] = S[(size_t)hi * 128 + tid];
    }
    __syncthreads();

    const float* P = ((t == 0) ? P0 : (t == 1) ? P1 : (t == 2) ? P2 :
                      (t == 3) ? P3 : P4) + (size_t)hi * SLAB;

    float4 p[8];
    float4 cp = make_float4(0.f, 0.f, 0.f, 0.f);
    #pragma unroll
    for (int jj = 0; jj < 8; jj++) {
        int j = part * 8 + jj;
        p[jj] = __ldcs((const float4*)(P + j * 128 + c0));
        float kj = k_s[j];
        cp.x += kj * p[jj].x;
        cp.y += kj * p[jj].y;
        cp.z += kj * p[jj].z;
        cp.w += kj * p[jj].w;
    }
    red4[part][cq] = cp;
    __syncthreads();

    float4 contr = make_float4(0.f, 0.f, 0.f, 0.f);
    #pragma unroll
    for (int pp = 0; pp < 16; pp++) {
        float4 r = red4[pp][cq];
        contr.x += r.x; contr.y += r.y; contr.z += r.z; contr.w += r.w;
    }

    float al = g_AL[hi];
    float ba = g_BA[hi];
    float* op = out + OFF_SM + (size_t)t * SM_SZ + (size_t)hi * SLAB;

    if (t == 4) {
        // D_k[i,j,c] = u_i*delta_{jc} - ba_i*S[i,c]*k_j ; rec term shared
        float u = g_U[hi];
        float Ax = ba * contr.x + ba * S_s[c0 + 0];
        float Ay = ba * contr.y + ba * S_s[c0 + 1];
        float Az = ba * contr.z + ba * S_s[c0 + 2];
        float Aw = ba * contr.w + ba * S_s[c0 + 3];
        #pragma unroll
        for (int jj = 0; jj < 8; jj++) {
            int j = part * 8 + jj;
            float kj = k_s[j];
            float4 v;
            v.x = al * p[jj].x - Ax * kj;
            v.y = al * p[jj].y - Ay * kj;
            v.z = al * p[jj].z - Az * kj;
            v.w = al * p[jj].w - Aw * kj;
            if (j == c0 + 0) v.x += u;
            if (j == c0 + 1) v.y += u;
            if (j == c0 + 2) v.z += u;
            if (j == c0 + 3) v.w += u;
            __stcs((float4*)(op + j * 128 + c0), v);
        }
    } else {
        // direct terms live only in column c == i
        float cfK, cfS = 0.f;
        if (t == 0)       cfK = g_CW[hi];
        else if (t == 1) { cfK = -g_CZ2[hi]; cfS = g_ALP[hi]; }
        else if (t == 2)  cfK = g_CB[hi];
        else              cfK = g_CV[hi];
        float fx = (c0 + 0 == i) ? 1.f : 0.f;
        float fy = (c0 + 1 == i) ? 1.f : 0.f;
        float fz = (c0 + 2 == i) ? 1.f : 0.f;
        float fw = (c0 + 3 == i) ? 1.f : 0.f;
        float bcx = ba * contr.x, bcy = ba * contr.y;
        float bcz = ba * contr.z, bcw = ba * contr.w;
        #pragma unroll
        for (int jj = 0; jj < 8; jj++) {
            int j = part * 8 + jj;
            float kj = k_s[j];
            float dterm = cfK * kj + cfS * S_s[j];
            float4 v;
            v.x = al * p[jj].x - bcx * kj + fx * dterm;
            v.y = al * p[jj].y - bcy * kj + fy * dterm;
            v.z = al * p[jj].z - bcz * kj + fz * dterm;
            v.w = al * p[jj].w - bcw * kj + fw * dterm;
            __stcs((float4*)(op + j * 128 + c0), v);
        }
    }
}

extern "C" void kernel_launch(void* const* d_in, const int* in_sizes, int n_in,
                              void* d_out, int out_size) {
    const float* x    = (const float*)d_in[0];
    const float* S    = (const float*)d_in[1];
    const float* sm_w = (const float*)d_in[2];
    const float* sm_z = (const float*)d_in[3];
    const float* sm_b = (const float*)d_in[4];
    const float* sm_v = (const float*)d_in[5];
    const float* sm_k = (const float*)d_in[6];
    const float* W_w  = (const float*)d_in[7];
    const float* W_z  = (const float*)d_in[8];
    const float* W_b  = (const float*)d_in[9];
    const float* W_v  = (const float*)d_in[10];
    const float* W_k  = (const float*)d_in[11];
    const float* W_q  = (const float*)d_in[12];
    const float* W_o  = (const float*)d_in[13];
    const float* b_o  = (const float*)d_in[14];
    float* out = (float*)d_out;

    head_kernel<<<HEAD_BLKS, 256>>>(x, S, W_w, W_z, W_b, W_v, W_k, W_q, out);
    slab_kernel<<<10240, 256>>>(sm_w, sm_z, sm_b, sm_v, sm_k, S, W_o, b_o, out);
}